// round 10
// baseline (speedup 1.0000x reference)
#include <cuda_runtime.h>

// EKVConv2d, warp-per-pixel / lane-per-output-channel, ballot-compacted.
//
// out[b,o,h,w] = ALPHA * sum_{c,kh,kw} [ sp(clip(d*inv,±30))^2 - sp(clip((d-VD)*inv,±30))^2 ]
// Work in log2 domain: a = d*inv*log2e, clip ±30*log2e, e = 2^a  (single EX2).
// Exact-zero: if a1 <= -CLIP both args clip equal -> s1==s2 -> term exactly 0.
// Patch element can contribute to ANY o only if xl > min_o(thl[o,ck]) - CLIP.
// ~5% pass; warp scans 144 elems once per pixel (uniform), ballot-compacts,
// evaluates actives branchlessly across lanes (lane = o).
//
// R10: theta preprocessing hoisted to a one-block prep kernel (device globals);
// 1024 CTAs (WSEG=16) for ~2x occupancy; log2-domain EX2; coalesced epilogue.

#define W_ 64
#define H_ 64
#define C_ 16
#define O_ 32
#define B_ 4
#define WSEG 16
#define TW (WSEG + 2)        // 18
#define NT 256
#define FULLMASK 0xffffffffu

#define INVL2  36.99218f     // 1/(1.5*0.026) * log2(e)
#define VDIL2  3.6992181f    // 0.1 * INVL2
#define CLIP   43.280851f    // 30 * log2(e)
#define ALPHA_ 0.0005625f

__device__ float thT_g[144 * 32];   // theta*INVL2, transposed [ck][o]
__device__ float thr_g[160];        // per-ck threshold (padded)

__device__ __forceinline__ float ex2(float x) {
    float r; asm("ex2.approx.ftz.f32 %0, %1;" : "=f"(r) : "f"(x)); return r;
}

__device__ __forceinline__ float sp_branchless(float e) {
    // softplus from e = exp(arg); poly for e<0.04 (rel err < 1e-6), else log1p
    float p = e * fmaf(e, fmaf(e, fmaf(e, -0.25f, 0.33333334f), -0.5f), 1.0f);
    float l = __logf(1.0f + e);
    return (e < 0.04f) ? p : l;
}

__global__ void prep_kernel(const float* __restrict__ theta) {
    int ck = threadIdx.x;
    if (ck < 144) {
        float m = 1e30f;
#pragma unroll
        for (int o = 0; o < O_; ++o) {
            float t = theta[o * 144 + ck] * INVL2;
            thT_g[ck * 32 + o] = t;
            m = fminf(m, t);
        }
        thr_g[ck] = m - CLIP;
    } else if (ck < 160) {
        thr_g[ck] = 1e30f;
    }
}

__global__ __launch_bounds__(NT) void ekv_kernel(const float* __restrict__ x,
                                                 float* __restrict__ out) {
    __shared__ float thT[144 * 32];      // [ck][o], stride 32 -> LDS bank = lane
    __shared__ float xt[C_ * 3 * TW];    // x*INVL2 tile [c][row3][col18]
    __shared__ float xpose[O_ * 17];     // epilogue transpose, stride 17

    const int tid  = threadIdx.x;
    const int lane = tid & 31;
    const int wid  = tid >> 5;           // 0..7
    const int w0 = blockIdx.x * WSEG;
    const int h  = blockIdx.y;
    const int b  = blockIdx.z;

    // ---- copy precomputed theta (coalesced float4, L2-resident) ----
    {
        const float4* src = (const float4*)thT_g;
        float4* dst = (float4*)thT;
#pragma unroll
        for (int i = 0; i < 5; ++i) {
            int idx = tid + i * NT;
            if (idx < 1152) dst[idx] = src[idx];
        }
    }

    // ---- x tile (rows h-1..h+1, cols w0-1..w0+16), scaled, zero-padded ----
    for (int i = tid; i < C_ * 3 * TW; i += NT) {
        int c   = i / (3 * TW);
        int rem = i - c * (3 * TW);
        int r   = rem / TW;
        int col = rem - r * TW;
        int gh = h - 1 + r;
        int gw = w0 - 1 + col;
        float v = 0.0f;
        if ((unsigned)gh < (unsigned)H_ && (unsigned)gw < (unsigned)W_)
            v = x[((b * C_ + c) * H_ + gh) * W_ + gw] * INVL2;
        xt[i] = v;
    }

    // ---- per-lane scan constants (registers) ----
    int   rdtab[5];
    float rthr[5];
#pragma unroll
    for (int it = 0; it < 5; ++it) {
        int ck = it * 32 + lane;
        int off = 0;
        if (ck < 144) {
            int c  = ck / 9;
            int k  = ck - 9 * c;
            int dh = k / 3;
            int dw = k - 3 * dh;
            off = (3 * c + dh) * TW + dw;
        }
        rdtab[it] = off;
        rthr[it]  = thr_g[ck];
    }
    __syncthreads();

    // ---- main: warp wid handles pixels pl = wid*2, wid*2+1; lane = o ----
#pragma unroll
    for (int j = 0; j < 2; ++j) {
        const int pl = wid * 2 + j;
        float acc = 0.0f;

#pragma unroll
        for (int it = 0; it < 5; ++it) {
            const int ckbase = it * 32;
            float xv = xt[pl + rdtab[it]];
            unsigned m = __ballot_sync(FULLMASK, xv > rthr[it]);
            while (m) {
                int src = __ffs(m) - 1;
                m &= m - 1;
                float xb  = __shfl_sync(FULLMASK, xv, src);
                float th  = thT[((ckbase + src) << 5) + lane];
                float a1  = xb - th;
                float a1c = fminf(fmaxf(a1, -CLIP), CLIP);
                float a2c = fminf(fmaxf(a1 - VDIL2, -CLIP), CLIP);
                float e1 = ex2(a1c);
                float e2 = ex2(a2c);
                float s1 = sp_branchless(e1);
                float s2 = sp_branchless(e2);
                // forced FMUL/FSUB (no FFMA contraction): s1==s2 -> exactly 0
                float t = __fsub_rn(__fmul_rn(s1, s1), __fmul_rn(s2, s2));
                acc = __fadd_rn(acc, t);
            }
        }
        xpose[lane * 17 + pl] = ALPHA_ * acc;
    }
    __syncthreads();

    // ---- coalesced epilogue: [o][pw] rows, 16 contiguous floats each ----
#pragma unroll
    for (int i = 0; i < 2; ++i) {
        int idx = tid + i * NT;          // 0..511
        int o  = idx >> 4;
        int pw = idx & 15;
        out[((b * O_ + o) * H_ + h) * W_ + w0 + pw] = xpose[o * 17 + pw];
    }
}

extern "C" void kernel_launch(void* const* d_in, const int* in_sizes, int n_in,
                              void* d_out, int out_size) {
    const float* x     = (const float*)d_in[0];
    const float* theta = (const float*)d_in[1];
    float* out         = (float*)d_out;
    prep_kernel<<<1, 160>>>(theta);
    dim3 grid(W_ / WSEG, H_, B_);   // (4, 64, 4) = 1024 CTAs
    ekv_kernel<<<grid, NT>>>(x, out);
}

// round 11
// speedup vs baseline: 1.0167x; 1.0167x over previous
#include <cuda_runtime.h>

// EKVConv2d, warp-per-pixel / lane-per-output-channel, ballot-compacted.
//
// out[b,o,h,w] = ALPHA * sum_{c,kh,kw} [ sp(clip(d*inv,±30))^2 - sp(clip((d-VD)*inv,±30))^2 ]
// Work in log2 domain: a = d*inv*log2e, clip ±30*log2e, e = 2^a (single EX2).
// Exact-zero: if a1 <= -CLIP both args clip equal -> s1==s2 -> term exactly 0.
// Patch element contributes to ANY o only if xl > min_o(thl[o,ck]) - CLIP (~5% pass).
// Warp scans 144 elems once per pixel (warp-uniform), ballot-compacts, evaluates
// actives branchlessly across lanes (lane = o), two actives per iteration.
//
// R11: prep folded back into main kernel (coalesced transpose — the R10 separate
// prep launch cost ~5us of wall clock); dual-bit ballot loop for MUFU/issue ILP.

#define W_ 64
#define H_ 64
#define C_ 16
#define O_ 32
#define B_ 4
#define WSEG 16
#define TW (WSEG + 2)        // 18
#define NT 256
#define FULLMASK 0xffffffffu

#define INVL2  36.99218f     // 1/(1.5*0.026) * log2(e)
#define VDIL2  3.6992181f    // 0.1 * INVL2
#define CLIP   43.280851f    // 30 * log2(e)
#define ALPHA_ 0.0005625f

__device__ __forceinline__ float ex2(float x) {
    float r; asm("ex2.approx.ftz.f32 %0, %1;" : "=f"(r) : "f"(x)); return r;
}

__device__ __forceinline__ float sp_branchless(float e) {
    // softplus from e = exp(arg); poly for e<0.04 (rel err < 1e-6), else log1p
    float p = e * fmaf(e, fmaf(e, fmaf(e, -0.25f, 0.33333334f), -0.5f), 1.0f);
    float l = __logf(1.0f + e);
    return (e < 0.04f) ? p : l;
}

// Evaluate one compacted (xb, th) pair; exact 0 when xb pushes both clips equal.
__device__ __forceinline__ float eval_term(float xb, float th) {
    float a1  = xb - th;
    float a1c = fminf(fmaxf(a1, -CLIP), CLIP);
    float a2c = fminf(fmaxf(a1 - VDIL2, -CLIP), CLIP);
    float e1 = ex2(a1c);
    float e2 = ex2(a2c);
    float s1 = sp_branchless(e1);
    float s2 = sp_branchless(e2);
    // forced FMUL/FSUB (no FFMA contraction): s1==s2 -> exactly 0
    return __fsub_rn(__fmul_rn(s1, s1), __fmul_rn(s2, s2));
}

__global__ __launch_bounds__(NT) void ekv_kernel(const float* __restrict__ x,
                                                 const float* __restrict__ theta,
                                                 float* __restrict__ out) {
    __shared__ float thT[144 * 33];      // theta*INVL2 transposed [ck][o], stride 33
    __shared__ float thr[160];           // per-ck threshold (padded)
    __shared__ float xt[C_ * 3 * TW];    // x*INVL2 tile [c][row3][col18]
    __shared__ float xpose[O_ * 17];     // epilogue transpose, stride 17

    const int tid  = threadIdx.x;
    const int lane = tid & 31;
    const int wid  = tid >> 5;           // 0..7
    const int w0 = blockIdx.x * WSEG;
    const int h  = blockIdx.y;
    const int b  = blockIdx.z;

    // ---- theta: coalesced read, scaled, scattered transpose into smem ----
#pragma unroll
    for (int i = 0; i < 18; ++i) {
        int idx = tid + i * NT;          // 0..4607
        int o  = idx / 144;
        int ck = idx - o * 144;
        thT[ck * 33 + o] = theta[idx] * INVL2;
    }

    // ---- x tile (rows h-1..h+1, cols w0-1..w0+16), scaled, zero-padded ----
    for (int i = tid; i < C_ * 3 * TW; i += NT) {
        int c   = i / (3 * TW);
        int rem = i - c * (3 * TW);
        int r   = rem / TW;
        int col = rem - r * TW;
        int gh = h - 1 + r;
        int gw = w0 - 1 + col;
        float v = 0.0f;
        if ((unsigned)gh < (unsigned)H_ && (unsigned)gw < (unsigned)W_)
            v = x[((b * C_ + c) * H_ + gh) * W_ + gw] * INVL2;
        xt[i] = v;
    }
    __syncthreads();

    // ---- per-ck threshold: min over o (stride-33 -> conflict-free) ----
    if (tid < 144) {
        const float* row = &thT[tid * 33];
        float m = row[0];
#pragma unroll
        for (int o = 1; o < O_; ++o) m = fminf(m, row[o]);
        thr[tid] = m - CLIP;
    } else if (tid < 160) {
        thr[tid] = 1e30f;
    }
    __syncthreads();

    // ---- per-lane scan constants (registers) ----
    int   rdtab[5];
    float rthr[5];
#pragma unroll
    for (int it = 0; it < 5; ++it) {
        int ck = it * 32 + lane;
        int off = 0;
        if (ck < 144) {
            int c  = ck / 9;
            int k  = ck - 9 * c;
            int dh = k / 3;
            int dw = k - 3 * dh;
            off = (3 * c + dh) * TW + dw;
        }
        rdtab[it] = off;
        rthr[it]  = thr[ck];
    }

    // ---- main: warp wid handles pixels pl = wid*2, wid*2+1; lane = o ----
#pragma unroll
    for (int j = 0; j < 2; ++j) {
        const int pl = wid * 2 + j;
        float acc = 0.0f;

#pragma unroll
        for (int it = 0; it < 5; ++it) {
            const int ckbase = it * 32;
            float xv = xt[pl + rdtab[it]];
            unsigned m = __ballot_sync(FULLMASK, xv > rthr[it]);
            while (m) {
                int src0 = __ffs(m) - 1;
                m &= m - 1;
                bool has2 = (m != 0);
                int src1 = has2 ? (__ffs(m) - 1) : src0;
                m &= m - 1;
                float xb0 = __shfl_sync(FULLMASK, xv, src0);
                float xb1 = __shfl_sync(FULLMASK, xv, src1);
                if (!has2) xb1 = -1e30f;   // clips both args equal -> term exactly 0
                float th0 = thT[(ckbase + src0) * 33 + lane];
                float th1 = thT[(ckbase + src1) * 33 + lane];
                float t0 = eval_term(xb0, th0);
                float t1 = eval_term(xb1, th1);
                acc = __fadd_rn(acc, __fadd_rn(t0, t1));
            }
        }
        xpose[lane * 17 + pl] = ALPHA_ * acc;
    }
    __syncthreads();

    // ---- coalesced epilogue: [o][pw] rows, 16 contiguous floats each ----
#pragma unroll
    for (int i = 0; i < 2; ++i) {
        int idx = tid + i * NT;          // 0..511
        int o  = idx >> 4;
        int pw = idx & 15;
        out[((b * O_ + o) * H_ + h) * W_ + w0 + pw] = xpose[o * 17 + pw];
    }
}

extern "C" void kernel_launch(void* const* d_in, const int* in_sizes, int n_in,
                              void* d_out, int out_size) {
    const float* x     = (const float*)d_in[0];
    const float* theta = (const float*)d_in[1];
    float* out         = (float*)d_out;
    dim3 grid(W_ / WSEG, H_, B_);   // (4, 64, 4) = 1024 CTAs
    ekv_kernel<<<grid, NT>>>(x, theta, out);
}

// round 12
// speedup vs baseline: 1.0554x; 1.0381x over previous
#include <cuda_runtime.h>

// EKVConv2d, warp-per-pixel / lane-per-output-channel, ballot-compacted.
//
// out[b,o,h,w] = ALPHA * sum_{c,kh,kw} [ sp(clip(d*inv,±30))^2 - sp(clip((d-VD)*inv,±30))^2 ]
// Fully log2 domain: a = d*inv*log2e (clip ±30*log2e), e = 2^a, and softplus kept in
// log2 units s' = log2(1+e) = sp/ln2; final scale ALPHA*ln2^2 applied once.
// Exact-zero: a1 <= -CLIP -> both args clip equal -> s1'==s2' -> term exactly 0.
// Patch element contributes to ANY o only if xl > min_o(thl[o,ck]) - CLIP (~5% pass).
// Warp scans 144 elems once per pixel (warp-uniform), ballot-compacts, evaluates
// actives branchlessly across lanes (lane = o), two actives per iteration.
//
// R12: log2-unit softplus (no ln-conversion FMULs), select predicate on a (not e),
// front-loaded scan (5 LDS + 5 ballots batched before draining).

#define W_ 64
#define H_ 64
#define C_ 16
#define O_ 32
#define B_ 4
#define WSEG 16
#define TW (WSEG + 2)        // 18
#define NT 256
#define FULLMASK 0xffffffffu

#define INVL2  36.99218f       // 1/(1.5*0.026) * log2(e)
#define VDIL2  3.6992181f      // 0.1 * INVL2
#define CLIP   43.280851f      // 30 * log2(e)
#define ALPHA_EFF 2.7025482e-4f  // ALPHA * ln(2)^2

__device__ __forceinline__ float ex2(float x) {
    float r; asm("ex2.approx.ftz.f32 %0, %1;" : "=f"(r) : "f"(x)); return r;
}
__device__ __forceinline__ float lg2(float x) {
    float r; asm("lg2.approx.ftz.f32 %0, %1;" : "=f"(r) : "f"(x)); return r;
}

// softplus in log2 units: s' = log2(1+2^a), given a (clipped) and e = 2^a.
// a < -4.6438 (e < 0.04): poly log2(1+e) = e*log2e*(1 - e/2 + e^2/3 - e^3/4),
// rel err < 1e-6.  Else lg2(1+e).
__device__ __forceinline__ float sp2(float a, float e) {
    float p = e * fmaf(e, fmaf(e, fmaf(e, -0.36067376f, 0.48089834f),
                               -0.7213475f), 1.4426950f);
    float l = lg2(1.0f + e);
    return (a < -4.6438562f) ? p : l;
}

// One compacted (xb, th) term; exact 0 when both clips coincide.
__device__ __forceinline__ float eval_term(float xb, float th) {
    float a1  = xb - th;
    float a1c = fminf(fmaxf(a1, -CLIP), CLIP);
    float a2c = fminf(fmaxf(a1 - VDIL2, -CLIP), CLIP);
    float e1 = ex2(a1c);
    float e2 = ex2(a2c);
    float s1 = sp2(a1c, e1);
    float s2 = sp2(a2c, e2);
    // forced FMUL/FSUB (no FFMA contraction): s1==s2 -> exactly 0
    return __fsub_rn(__fmul_rn(s1, s1), __fmul_rn(s2, s2));
}

__global__ __launch_bounds__(NT) void ekv_kernel(const float* __restrict__ x,
                                                 const float* __restrict__ theta,
                                                 float* __restrict__ out) {
    __shared__ float thT[144 * 33];      // theta*INVL2 transposed [ck][o], stride 33
    __shared__ float thr[160];           // per-ck threshold (padded)
    __shared__ float xt[C_ * 3 * TW];    // x*INVL2 tile [c][row3][col18]
    __shared__ float xpose[O_ * 17];     // epilogue transpose, stride 17

    const int tid  = threadIdx.x;
    const int lane = tid & 31;
    const int wid  = tid >> 5;           // 0..7
    const int w0 = blockIdx.x * WSEG;
    const int h  = blockIdx.y;
    const int b  = blockIdx.z;

    // ---- theta: coalesced read, scaled, scattered transpose into smem ----
#pragma unroll
    for (int i = 0; i < 18; ++i) {
        int idx = tid + i * NT;          // 0..4607
        int o  = idx / 144;
        int ck = idx - o * 144;
        thT[ck * 33 + o] = theta[idx] * INVL2;
    }

    // ---- x tile (rows h-1..h+1, cols w0-1..w0+16), scaled, zero-padded ----
    for (int i = tid; i < C_ * 3 * TW; i += NT) {
        int c   = i / (3 * TW);
        int rem = i - c * (3 * TW);
        int r   = rem / TW;
        int col = rem - r * TW;
        int gh = h - 1 + r;
        int gw = w0 - 1 + col;
        float v = 0.0f;
        if ((unsigned)gh < (unsigned)H_ && (unsigned)gw < (unsigned)W_)
            v = x[((b * C_ + c) * H_ + gh) * W_ + gw] * INVL2;
        xt[i] = v;
    }
    __syncthreads();

    // ---- per-ck threshold: min over o (stride-33 -> conflict-free) ----
    if (tid < 144) {
        const float* row = &thT[tid * 33];
        float m = row[0];
#pragma unroll
        for (int o = 1; o < O_; ++o) m = fminf(m, row[o]);
        thr[tid] = m - CLIP;
    } else if (tid < 160) {
        thr[tid] = 1e30f;
    }
    __syncthreads();

    // ---- per-lane scan constants (registers) ----
    int   rdtab[5];
    float rthr[5];
#pragma unroll
    for (int it = 0; it < 5; ++it) {
        int ck = it * 32 + lane;
        int off = 0;
        if (ck < 144) {
            int c  = ck / 9;
            int k  = ck - 9 * c;
            int dh = k / 3;
            int dw = k - 3 * dh;
            off = (3 * c + dh) * TW + dw;
        }
        rdtab[it] = off;
        rthr[it]  = thr[ck];
    }

    // ---- main: warp wid handles pixels pl = wid*2, wid*2+1; lane = o ----
#pragma unroll
    for (int j = 0; j < 2; ++j) {
        const int pl = wid * 2 + j;
        float acc = 0.0f;

        // front-load scan: 5 independent LDS, then 5 ballots
        float    xvs[5];
        unsigned ms[5];
#pragma unroll
        for (int it = 0; it < 5; ++it) xvs[it] = xt[pl + rdtab[it]];
#pragma unroll
        for (int it = 0; it < 5; ++it)
            ms[it] = __ballot_sync(FULLMASK, xvs[it] > rthr[it]);

#pragma unroll
        for (int it = 0; it < 5; ++it) {
            const int ckbase = it * 32;
            float xv = xvs[it];
            unsigned m = ms[it];
            while (m) {
                int src0 = __ffs(m) - 1;
                m &= m - 1;
                bool has2 = (m != 0);
                int src1 = has2 ? (__ffs(m) - 1) : src0;
                m &= m - 1;
                float xb0 = __shfl_sync(FULLMASK, xv, src0);
                float xb1 = __shfl_sync(FULLMASK, xv, src1);
                if (!has2) xb1 = -1e30f;   // clips both args equal -> exact 0
                float th0 = thT[(ckbase + src0) * 33 + lane];
                float th1 = thT[(ckbase + src1) * 33 + lane];
                float t0 = eval_term(xb0, th0);
                float t1 = eval_term(xb1, th1);
                acc = __fadd_rn(acc, __fadd_rn(t0, t1));
            }
        }
        xpose[lane * 17 + pl] = ALPHA_EFF * acc;
    }
    __syncthreads();

    // ---- coalesced epilogue: [o][pw] rows, 16 contiguous floats each ----
#pragma unroll
    for (int i = 0; i < 2; ++i) {
        int idx = tid + i * NT;          // 0..511
        int o  = idx >> 4;
        int pw = idx & 15;
        out[((b * O_ + o) * H_ + h) * W_ + w0 + pw] = xpose[o * 17 + pw];
    }
}

extern "C" void kernel_launch(void* const* d_in, const int* in_sizes, int n_in,
                              void* d_out, int out_size) {
    const float* x     = (const float*)d_in[0];
    const float* theta = (const float*)d_in[1];
    float* out         = (float*)d_out;
    dim3 grid(W_ / WSEG, H_, B_);   // (4, 64, 4) = 1024 CTAs
    ekv_kernel<<<grid, NT>>>(x, theta, out);
}

// round 14
// speedup vs baseline: 1.1575x; 1.0968x over previous
#include <cuda_runtime.h>

// EKVConv2d, warp-per-pixel / lane-per-output-channel, ballot-compacted.
//
// out[b,o,h,w] = ALPHA * sum_{c,kh,kw} [ sp(clip(d*inv,±30))^2 - sp(clip((d-VD)*inv,±30))^2 ]
// Fully log2 domain: a = d*inv*log2e (clip ±30*log2e), e = 2^a, and softplus kept in
// log2 units s' = log2(1+e) = sp/ln2; final scale ALPHA*ln2^2 applied once.
// Exact-zero: a1 <= -CLIP -> both args clip equal -> s1'==s2' -> term exactly 0.
// Patch element contributes to ANY o only if xl > min_o(thl[o,ck]) - CLIP (~5% pass).
// Warp scans 144 elems once per pixel (warp-uniform), ballot-compacts, evaluates
// actives branchlessly across lanes (lane = o), two actives per iteration.
//
// R12: log2-unit softplus (no ln-conversion FMULs), select predicate on a (not e),
// front-loaded scan (5 LDS + 5 ballots batched before draining).

#define W_ 64
#define H_ 64
#define C_ 16
#define O_ 32
#define B_ 4
#define WSEG 16
#define TW (WSEG + 2)        // 18
#define NT 256
#define FULLMASK 0xffffffffu

#define INVL2  36.99218f       // 1/(1.5*0.026) * log2(e)
#define VDIL2  3.6992181f      // 0.1 * INVL2
#define CLIP   43.280851f      // 30 * log2(e)
#define ALPHA_EFF 2.7025482e-4f  // ALPHA * ln(2)^2

__device__ __forceinline__ float ex2(float x) {
    float r; asm("ex2.approx.ftz.f32 %0, %1;" : "=f"(r) : "f"(x)); return r;
}
__device__ __forceinline__ float lg2(float x) {
    float r; asm("lg2.approx.ftz.f32 %0, %1;" : "=f"(r) : "f"(x)); return r;
}

// softplus in log2 units: s' = log2(1+2^a), given a (clipped) and e = 2^a.
// a < -4.6438 (e < 0.04): poly log2(1+e) = e*log2e*(1 - e/2 + e^2/3 - e^3/4),
// rel err < 1e-6.  Else lg2(1+e).
__device__ __forceinline__ float sp2(float a, float e) {
    float p = e * fmaf(e, fmaf(e, fmaf(e, -0.36067376f, 0.48089834f),
                               -0.7213475f), 1.4426950f);
    float l = lg2(1.0f + e);
    return (a < -4.6438562f) ? p : l;
}

// One compacted (xb, th) term; exact 0 when both clips coincide.
__device__ __forceinline__ float eval_term(float xb, float th) {
    float a1  = xb - th;
    float a1c = fminf(fmaxf(a1, -CLIP), CLIP);
    float a2c = fminf(fmaxf(a1 - VDIL2, -CLIP), CLIP);
    float e1 = ex2(a1c);
    float e2 = ex2(a2c);
    float s1 = sp2(a1c, e1);
    float s2 = sp2(a2c, e2);
    // forced FMUL/FSUB (no FFMA contraction): s1==s2 -> exactly 0
    return __fsub_rn(__fmul_rn(s1, s1), __fmul_rn(s2, s2));
}

__global__ __launch_bounds__(NT) void ekv_kernel(const float* __restrict__ x,
                                                 const float* __restrict__ theta,
                                                 float* __restrict__ out) {
    __shared__ float thT[144 * 33];      // theta*INVL2 transposed [ck][o], stride 33
    __shared__ float thr[160];           // per-ck threshold (padded)
    __shared__ float xt[C_ * 3 * TW];    // x*INVL2 tile [c][row3][col18]
    __shared__ float xpose[O_ * 17];     // epilogue transpose, stride 17

    const int tid  = threadIdx.x;
    const int lane = tid & 31;
    const int wid  = tid >> 5;           // 0..7
    const int w0 = blockIdx.x * WSEG;
    const int h  = blockIdx.y;
    const int b  = blockIdx.z;

    // ---- theta: coalesced read, scaled, scattered transpose into smem ----
#pragma unroll
    for (int i = 0; i < 18; ++i) {
        int idx = tid + i * NT;          // 0..4607
        int o  = idx / 144;
        int ck = idx - o * 144;
        thT[ck * 33 + o] = theta[idx] * INVL2;
    }

    // ---- x tile (rows h-1..h+1, cols w0-1..w0+16), scaled, zero-padded ----
    for (int i = tid; i < C_ * 3 * TW; i += NT) {
        int c   = i / (3 * TW);
        int rem = i - c * (3 * TW);
        int r   = rem / TW;
        int col = rem - r * TW;
        int gh = h - 1 + r;
        int gw = w0 - 1 + col;
        float v = 0.0f;
        if ((unsigned)gh < (unsigned)H_ && (unsigned)gw < (unsigned)W_)
            v = x[((b * C_ + c) * H_ + gh) * W_ + gw] * INVL2;
        xt[i] = v;
    }
    __syncthreads();

    // ---- per-ck threshold: min over o (stride-33 -> conflict-free) ----
    if (tid < 144) {
        const float* row = &thT[tid * 33];
        float m = row[0];
#pragma unroll
        for (int o = 1; o < O_; ++o) m = fminf(m, row[o]);
        thr[tid] = m - CLIP;
    } else if (tid < 160) {
        thr[tid] = 1e30f;
    }
    __syncthreads();

    // ---- per-lane scan constants (registers) ----
    int   rdtab[5];
    float rthr[5];
#pragma unroll
    for (int it = 0; it < 5; ++it) {
        int ck = it * 32 + lane;
        int off = 0;
        if (ck < 144) {
            int c  = ck / 9;
            int k  = ck - 9 * c;
            int dh = k / 3;
            int dw = k - 3 * dh;
            off = (3 * c + dh) * TW + dw;
        }
        rdtab[it] = off;
        rthr[it]  = thr[ck];
    }

    // ---- main: warp wid handles pixels pl = wid*2, wid*2+1; lane = o ----
#pragma unroll
    for (int j = 0; j < 2; ++j) {
        const int pl = wid * 2 + j;
        float acc = 0.0f;

        // front-load scan: 5 independent LDS, then 5 ballots
        float    xvs[5];
        unsigned ms[5];
#pragma unroll
        for (int it = 0; it < 5; ++it) xvs[it] = xt[pl + rdtab[it]];
#pragma unroll
        for (int it = 0; it < 5; ++it)
            ms[it] = __ballot_sync(FULLMASK, xvs[it] > rthr[it]);

#pragma unroll
        for (int it = 0; it < 5; ++it) {
            const int ckbase = it * 32;
            float xv = xvs[it];
            unsigned m = ms[it];
            while (m) {
                int src0 = __ffs(m) - 1;
                m &= m - 1;
                bool has2 = (m != 0);
                int src1 = has2 ? (__ffs(m) - 1) : src0;
                m &= m - 1;
                float xb0 = __shfl_sync(FULLMASK, xv, src0);
                float xb1 = __shfl_sync(FULLMASK, xv, src1);
                if (!has2) xb1 = -1e30f;   // clips both args equal -> exact 0
                float th0 = thT[(ckbase + src0) * 33 + lane];
                float th1 = thT[(ckbase + src1) * 33 + lane];
                float t0 = eval_term(xb0, th0);
                float t1 = eval_term(xb1, th1);
                acc = __fadd_rn(acc, __fadd_rn(t0, t1));
            }
        }
        xpose[lane * 17 + pl] = ALPHA_EFF * acc;
    }
    __syncthreads();

    // ---- coalesced epilogue: [o][pw] rows, 16 contiguous floats each ----
#pragma unroll
    for (int i = 0; i < 2; ++i) {
        int idx = tid + i * NT;          // 0..511
        int o  = idx >> 4;
        int pw = idx & 15;
        out[((b * O_ + o) * H_ + h) * W_ + w0 + pw] = xpose[o * 17 + pw];
    }
}

extern "C" void kernel_launch(void* const* d_in, const int* in_sizes, int n_in,
                              void* d_out, int out_size) {
    const float* x     = (const float*)d_in[0];
    const float* theta = (const float*)d_in[1];
    float* out         = (float*)d_out;
    dim3 grid(W_ / WSEG, H_, B_);   // (4, 64, 4) = 1024 CTAs
    ekv_kernel<<<grid, NT>>>(x, theta, out);
}